// round 8
// baseline (speedup 1.0000x reference)
#include <cuda_runtime.h>
#include <cuda_fp16.h>
#include <math.h>

#define NN 100000
#define NE 3200000
#define NBLK 391            // ceil(NN/256)

// ---------------- device scratch ----------------
__device__ int    g_flag64;
__device__ int    g_deg[NN];
__device__ int    g_rowptr[NN + 1];
__device__ int    g_cursor[NN];
__device__ int    g_bsum[NBLK];
__device__ int    g_bflag[NBLK];
__device__ int2   g_csr[NE];           // {src, weight-bits}, bucketed by dst
__device__ __half g_t0[NN * 8];        // x@W1                     (fp16, 8-wide)
__device__ __half g_h1[NN * 16];       // relu(agg1+b1)@W2         (fp16, 16-wide)
__device__ __half g_t2[NN * 8];        // relu(agg2+b2)@W3         (fp16, 8-wide)
__device__ __half g_h3[NN * 16];       // relu(agg3+b3)@W4 pad16   (fp16, 16-wide)

// ---------------- init: zero deg + scan flags, detect int64 vs int32 ------------
__global__ void k_init(const int* __restrict__ ei) {
    int i = blockIdx.x * 256 + threadIdx.x;
    if (i < NN) g_deg[i] = 0;
    if (i < NBLK) g_bflag[i] = 0;
    if (blockIdx.x == 0 && threadIdx.x < 32) {
        int v = 0;
        for (int j = threadIdx.x; j < 512; j += 32) v |= ei[2 * j + 1];
        for (int o = 16; o; o >>= 1) v |= __shfl_xor_sync(0xffffffffu, v, o);
        if (threadIdx.x == 0) g_flag64 = (v == 0) ? 1 : 0;
    }
}

// ---------------- degree count ----------------
__global__ void k_count(const int* __restrict__ ei) {
    int e = blockIdx.x * blockDim.x + threadIdx.x;  // NE divisible by 256
    int dst = g_flag64 ? ei[2 * (NE + e)] : ei[NE + e];
    atomicAdd(&g_deg[dst], 1);
}

// ---------------- single-pass exclusive scan with spin-lookback ----------------
// 391 blocks x 256 threads, all resident simultaneously => spin is safe.
__global__ void k_scan() {
    __shared__ int wsum[8];
    __shared__ int red[8];
    __shared__ int s_off;
    int bid = blockIdx.x, t = threadIdx.x;
    int lane = t & 31, wid = t >> 5;
    int i = bid * 256 + t;
    int val = (i < NN) ? g_deg[i] : 0;
    int v = val;
    #pragma unroll
    for (int o = 1; o < 32; o <<= 1) {
        int u = __shfl_up_sync(0xffffffffu, v, o);
        if (lane >= o) v += u;
    }
    if (lane == 31) wsum[wid] = v;
    __syncthreads();
    if (wid == 0 && lane < 8) {
        int w = wsum[lane];
        #pragma unroll
        for (int o = 1; o < 8; o <<= 1) {
            int u = __shfl_up_sync(0xFFu, w, o, 8);
            if (lane >= o) w += u;
        }
        wsum[lane] = w;
    }
    __syncthreads();
    int excl = (v - val) + (wid ? wsum[wid - 1] : 0);
    // publish this block's total
    if (t == 0) {
        g_bsum[bid] = wsum[7];
        __threadfence();
        atomicExch(&g_bflag[bid], 1);
    }
    // lookback: sum all predecessor totals
    int part = 0;
    for (int p = t; p < bid; p += 256) {
        while (atomicAdd(&g_bflag[p], 0) == 0) { }
        __threadfence();
        part += *((volatile int*)&g_bsum[p]);
    }
    #pragma unroll
    for (int o = 16; o; o >>= 1) part += __shfl_xor_sync(0xffffffffu, part, o);
    if (lane == 0) red[wid] = part;
    __syncthreads();
    if (t == 0) {
        int r = 0;
        #pragma unroll
        for (int j = 0; j < 8; j++) r += red[j];
        s_off = r;
    }
    __syncthreads();
    int rp = s_off + excl;
    if (i < NN) { g_rowptr[i] = rp; g_cursor[i] = rp; }
    if (i == 0) g_rowptr[NN] = NE;
}

// ---------------- fused: gemm1 (blocks 0..3124) || scatter (rest) ----------------
// gemm1: t0 = x @ W1 (100000x512 @ 512x8), warp per 4 nodes, fp16 output.
__global__ void k_fused(const float* __restrict__ x, const float* __restrict__ W1,
                        const int* __restrict__ ei, const float* __restrict__ ew) {
    __shared__ float Wt[8 * 512];
    if (blockIdx.x < 3125) {
        for (int idx = threadIdx.x; idx < 4096; idx += 256) {
            int o = idx >> 9, k = idx & 511;
            Wt[idx] = W1[k * 8 + o];
        }
        __syncthreads();
        int warp = (blockIdx.x * 256 + threadIdx.x) >> 5;
        int lane = threadIdx.x & 31;
        int nb = warp * 4;

        float acc[4][8];
        #pragma unroll
        for (int i = 0; i < 4; i++)
            #pragma unroll
            for (int o = 0; o < 8; o++) acc[i][o] = 0.f;

        #pragma unroll
        for (int j = 0; j < 4; j++) {
            int c = 4 * lane + 128 * j;
            float4 xv[4];
            #pragma unroll
            for (int i = 0; i < 4; i++)
                xv[i] = *(const float4*)(x + (size_t)(nb + i) * 512 + c);
            #pragma unroll
            for (int o = 0; o < 8; o++) {
                float4 wv = *(const float4*)(Wt + o * 512 + c);
                #pragma unroll
                for (int i = 0; i < 4; i++)
                    acc[i][o] += xv[i].x * wv.x + xv[i].y * wv.y + xv[i].z * wv.z + xv[i].w * wv.w;
            }
        }
        float myval = 0.f;
        #pragma unroll
        for (int i = 0; i < 4; i++)
            #pragma unroll
            for (int o = 0; o < 8; o++) {
                float r = acc[i][o];
                #pragma unroll
                for (int off = 16; off; off >>= 1) r += __shfl_xor_sync(0xffffffffu, r, off);
                if (lane == i * 8 + o) myval = r;
            }
        g_t0[(size_t)nb * 8 + lane] = __float2half(myval);
    } else {
        int e = (blockIdx.x - 3125) * 256 + threadIdx.x;
        int src, dst;
        if (g_flag64) { src = ei[2 * e]; dst = ei[2 * (NE + e)]; }
        else          { src = ei[e];     dst = ei[NE + e]; }
        int pos = atomicAdd(&g_cursor[dst], 1);
        g_csr[pos] = make_int2(src, __float_as_int(ew[e]));
    }
}

// ================= gathers =======================================================
// fp16 8-wide table, group of 4 lanes, lane f holds features {2f, 2f+1} as half2.
#define GATHER_H8(TINH2)                                                         \
    int s = g_rowptr[gid], e = g_rowptr[gid + 1];                                \
    unsigned gmask = 0xFu << (threadIdx.x & 28);                                 \
    float acc0 = 0.f, acc1 = 0.f;                                                \
    int i = s;                                                                   \
    for (; i + 4 <= e; i += 4) {                                                 \
        int2 my = g_csr[i + f];                                                  \
        _Pragma("unroll")                                                        \
        for (int k = 0; k < 4; k++) {                                            \
            int   sk = __shfl_sync(gmask, my.x, k, 4);                           \
            float wk = __int_as_float(__shfl_sync(gmask, my.y, k, 4));           \
            float2 v = __half22float2(TINH2[(size_t)sk * 4 + f]);                \
            acc0 += v.x * wk;  acc1 += v.y * wk;                                 \
        }                                                                        \
    }                                                                            \
    int rem = e - i;                                                             \
    if (rem) {                                                                   \
        int2 my = make_int2(0, 0);                                               \
        if (f < rem) my = g_csr[i + f];                                          \
        _Pragma("unroll")                                                        \
        for (int k = 0; k < 3; k++) {                                            \
            int   sk = __shfl_sync(gmask, my.x, k, 4);                           \
            float wk = __int_as_float(__shfl_sync(gmask, my.y, k, 4));           \
            if (k < rem) {                                                       \
                float2 v = __half22float2(TINH2[(size_t)sk * 4 + f]);            \
                acc0 += v.x * wk;  acc1 += v.y * wk;                             \
            }                                                                    \
        }                                                                        \
    }

// fp16 16-wide table, group of 8 lanes, lane f holds features {2f, 2f+1} as half2.
#define GATHER_H16(TINH2)                                                        \
    int s = g_rowptr[gid], e = g_rowptr[gid + 1];                                \
    unsigned gmask = 0xFFu << (threadIdx.x & 24);                                \
    float acc0 = 0.f, acc1 = 0.f;                                                \
    int i = s;                                                                   \
    for (; i + 8 <= e; i += 8) {                                                 \
        int2 my = g_csr[i + f];                                                  \
        _Pragma("unroll")                                                        \
        for (int k = 0; k < 8; k++) {                                            \
            int   sk = __shfl_sync(gmask, my.x, k, 8);                           \
            float wk = __int_as_float(__shfl_sync(gmask, my.y, k, 8));           \
            float2 v = __half22float2(TINH2[(size_t)sk * 8 + f]);                \
            acc0 += v.x * wk;  acc1 += v.y * wk;                                 \
        }                                                                        \
    }                                                                            \
    int rem = e - i;                                                             \
    if (rem) {                                                                   \
        int2 my = make_int2(0, 0);                                               \
        if (f < rem) my = g_csr[i + f];                                          \
        _Pragma("unroll")                                                        \
        for (int k = 0; k < 7; k++) {                                            \
            int   sk = __shfl_sync(gmask, my.x, k, 8);                           \
            float wk = __int_as_float(__shfl_sync(gmask, my.y, k, 8));           \
            if (k < rem) {                                                       \
                float2 v = __half22float2(TINH2[(size_t)sk * 8 + f]);            \
                acc0 += v.x * wk;  acc1 += v.y * wk;                             \
            }                                                                    \
        }                                                                        \
    }

// ---------------- layer 1: agg(t0) + b1, relu, @W2 (8->16), store half ----------
// group4: lane f owns input features {2f,2f+1}, writes output pairs {2f,2f+1},{2f+8,2f+9}
__global__ void k_agg1(const float* __restrict__ b1, const float* __restrict__ W2) {
    __shared__ float Ws[8 * 16];
    __shared__ float bs[8];
    if (threadIdx.x < 128) Ws[threadIdx.x] = W2[threadIdx.x];
    if (threadIdx.x < 8) bs[threadIdx.x] = b1[threadIdx.x];
    __syncthreads();
    int t = blockIdx.x * 256 + threadIdx.x;
    int gid = t >> 2, f = t & 3;
    if (gid >= NN) return;                       // group-uniform exit
    GATHER_H8(((const __half2*)g_t0))
    float h0 = fmaxf(acc0 + bs[2 * f], 0.f);
    float h1 = fmaxf(acc1 + bs[2 * f + 1], 0.f);
    unsigned m2 = 0xFu << (threadIdx.x & 28);
    float o0 = 0.f, o1 = 0.f, o2 = 0.f, o3 = 0.f;
    #pragma unroll
    for (int j = 0; j < 4; j++) {
        float a0 = __shfl_sync(m2, h0, j, 4);    // h[2j]
        float a1 = __shfl_sync(m2, h1, j, 4);    // h[2j+1]
        o0 += a0 * Ws[(2 * j) * 16 + 2 * f]     + a1 * Ws[(2 * j + 1) * 16 + 2 * f];
        o1 += a0 * Ws[(2 * j) * 16 + 2 * f + 1] + a1 * Ws[(2 * j + 1) * 16 + 2 * f + 1];
        o2 += a0 * Ws[(2 * j) * 16 + 2 * f + 8] + a1 * Ws[(2 * j + 1) * 16 + 2 * f + 8];
        o3 += a0 * Ws[(2 * j) * 16 + 2 * f + 9] + a1 * Ws[(2 * j + 1) * 16 + 2 * f + 9];
    }
    __half2* H = (__half2*)g_h1;
    H[(size_t)gid * 8 + f]     = __floats2half2_rn(o0, o1);
    H[(size_t)gid * 8 + f + 4] = __floats2half2_rn(o2, o3);
}

// ---------------- layer 2: agg(h1) + b2, relu, @W3 (16->8), store half ----------
__global__ void k_agg2(const float* __restrict__ b2, const float* __restrict__ W3) {
    __shared__ float Ws[16 * 8];
    __shared__ float bs[16];
    if (threadIdx.x < 128) Ws[threadIdx.x] = W3[threadIdx.x];
    if (threadIdx.x < 16) bs[threadIdx.x] = b2[threadIdx.x];
    __syncthreads();
    int t = blockIdx.x * 256 + threadIdx.x;
    int gid = t >> 3, f = t & 7;
    GATHER_H16(((const __half2*)g_h1))
    float h0 = fmaxf(acc0 + bs[2 * f], 0.f);
    float h1 = fmaxf(acc1 + bs[2 * f + 1], 0.f);
    float out = 0.f;
    #pragma unroll
    for (int k = 0; k < 8; k++) {
        float hk0 = __shfl_sync(0xffffffffu, h0, k, 8);
        float hk1 = __shfl_sync(0xffffffffu, h1, k, 8);
        out += hk0 * Ws[(2 * k) * 8 + f] + hk1 * Ws[(2 * k + 1) * 8 + f];
    }
    g_t2[(size_t)gid * 8 + f] = __float2half(out);
}

// ---------------- layer 3: agg(t2) + b3, relu, @W4 (8->10 pad16), store half -----
__global__ void k_agg3(const float* __restrict__ b3, const float* __restrict__ W4) {
    __shared__ float Ws[8 * 16];
    __shared__ float bs[8];
    if (threadIdx.x < 128) {
        int k = threadIdx.x >> 4, o = threadIdx.x & 15;
        Ws[threadIdx.x] = (o < 10) ? W4[k * 10 + o] : 0.f;
    }
    if (threadIdx.x < 8) bs[threadIdx.x] = b3[threadIdx.x];
    __syncthreads();
    int t = blockIdx.x * 256 + threadIdx.x;
    int gid = t >> 2, f = t & 3;
    if (gid >= NN) return;
    GATHER_H8(((const __half2*)g_t2))
    float h0 = fmaxf(acc0 + bs[2 * f], 0.f);
    float h1 = fmaxf(acc1 + bs[2 * f + 1], 0.f);
    unsigned m2 = 0xFu << (threadIdx.x & 28);
    float o0 = 0.f, o1 = 0.f, o2 = 0.f, o3 = 0.f;
    #pragma unroll
    for (int j = 0; j < 4; j++) {
        float a0 = __shfl_sync(m2, h0, j, 4);
        float a1 = __shfl_sync(m2, h1, j, 4);
        o0 += a0 * Ws[(2 * j) * 16 + 2 * f]     + a1 * Ws[(2 * j + 1) * 16 + 2 * f];
        o1 += a0 * Ws[(2 * j) * 16 + 2 * f + 1] + a1 * Ws[(2 * j + 1) * 16 + 2 * f + 1];
        o2 += a0 * Ws[(2 * j) * 16 + 2 * f + 8] + a1 * Ws[(2 * j + 1) * 16 + 2 * f + 8];
        o3 += a0 * Ws[(2 * j) * 16 + 2 * f + 9] + a1 * Ws[(2 * j + 1) * 16 + 2 * f + 9];
    }
    __half2* H = (__half2*)g_h3;
    H[(size_t)gid * 8 + f]     = __floats2half2_rn(o0, o1);
    H[(size_t)gid * 8 + f + 4] = __floats2half2_rn(o2, o3);
}

// ---------------- layer 4: agg(h3) + b4, log_softmax over 10 classes ------------
__global__ void k_agg4(const float* __restrict__ b4, float* __restrict__ out) {
    __shared__ float bs[16];
    if (threadIdx.x < 16) bs[threadIdx.x] = (threadIdx.x < 10) ? b4[threadIdx.x] : 0.f;
    __syncthreads();
    int t = blockIdx.x * 256 + threadIdx.x;
    int gid = t >> 3, f = t & 7;
    GATHER_H16(((const __half2*)g_h3))
    float v0 = acc0 + bs[2 * f];
    float v1 = acc1 + bs[2 * f + 1];
    bool k0 = (2 * f) < 10, k1 = (2 * f + 1) < 10;
    float m = -INFINITY;
    if (k0) m = v0;
    if (k1) m = fmaxf(m, v1);
    #pragma unroll
    for (int off = 4; off; off >>= 1) m = fmaxf(m, __shfl_xor_sync(0xffffffffu, m, off, 8));
    float e0 = k0 ? expf(v0 - m) : 0.f;
    float e1 = k1 ? expf(v1 - m) : 0.f;
    float se = e0 + e1;
    #pragma unroll
    for (int off = 4; off; off >>= 1) se += __shfl_xor_sync(0xffffffffu, se, off, 8);
    float ls = logf(se);
    if (k0) out[(size_t)gid * 10 + 2 * f]     = v0 - m - ls;
    if (k1) out[(size_t)gid * 10 + 2 * f + 1] = v1 - m - ls;
}

// ---------------- launch ----------------
extern "C" void kernel_launch(void* const* d_in, const int* in_sizes, int n_in,
                              void* d_out, int out_size) {
    const float* x  = (const float*)d_in[0];
    const int*   ei = (const int*)d_in[1];
    const float* ew = (const float*)d_in[2];
    const float* W1 = (const float*)d_in[3];
    const float* b1 = (const float*)d_in[4];
    const float* W2 = (const float*)d_in[5];
    const float* b2 = (const float*)d_in[6];
    const float* W3 = (const float*)d_in[7];
    const float* b3 = (const float*)d_in[8];
    const float* W4 = (const float*)d_in[9];
    const float* b4 = (const float*)d_in[10];
    float* out = (float*)d_out;

    k_init<<<NBLK, 256>>>(ei);                    // 1
    k_count<<<NE / 256, 256>>>(ei);               // 2
    k_scan<<<NBLK, 256>>>();                      // 3
    k_fused<<<3125 + NE / 256, 256>>>(x, W1, ei, ew);  // 4  <- profiled next round

    k_agg1<<<(NN * 4 + 255) / 256, 256>>>(b1, W2);     // 5
    k_agg2<<<NN * 8 / 256, 256>>>(b2, W3);             // 6
    k_agg3<<<(NN * 4 + 255) / 256, 256>>>(b3, W4);     // 7
    k_agg4<<<NN * 8 / 256, 256>>>(b4, out);            // 8
}

// round 11
// speedup vs baseline: 1.1094x; 1.1094x over previous
#include <cuda_runtime.h>
#include <cuda_fp16.h>
#include <math.h>

#define NN 100000
#define NE 3200000
#define NBLK 391            // ceil(NN/256)

// ---------------- device scratch ----------------
__device__ int    g_flag64;
__device__ int    g_deg[NN];
__device__ int    g_rowptr[NN + 1];
__device__ int    g_cursor[NN];
__device__ int    g_bsum[NBLK];
__device__ int    g_bflag[NBLK];
__device__ int2   g_csr[NE];           // {src, weight-bits}, bucketed by dst
__device__ __half g_t0[NN * 8];        // x@W1                     (fp16, 8-wide)
__device__ __half g_h1[NN * 16];       // relu(agg1+b1)@W2         (fp16, 16-wide)
__device__ __half g_t2[NN * 8];        // relu(agg2+b2)@W3         (fp16, 8-wide)
__device__ __half g_h3[NN * 16];       // relu(agg3+b3)@W4 pad16   (fp16, 16-wide)

// ---------------- init: zero deg + scan flags, detect int64 vs int32 ------------
__global__ void k_init(const int* __restrict__ ei) {
    int i = blockIdx.x * 256 + threadIdx.x;
    if (i < NN) g_deg[i] = 0;
    if (i < NBLK) g_bflag[i] = 0;
    if (blockIdx.x == 0 && threadIdx.x < 32) {
        int v = 0;
        for (int j = threadIdx.x; j < 512; j += 32) v |= ei[2 * j + 1];
        for (int o = 16; o; o >>= 1) v |= __shfl_xor_sync(0xffffffffu, v, o);
        if (threadIdx.x == 0) g_flag64 = (v == 0) ? 1 : 0;
    }
}

// ---------------- degree count ----------------
__global__ void __launch_bounds__(256) k_count(const int* __restrict__ ei) {
    int e = blockIdx.x * blockDim.x + threadIdx.x;  // NE divisible by 256
    int dst;
    if (g_flag64) {
        dst = (int)__ldcs((const long long*)ei + NE + e);
    } else {
        dst = __ldcs(ei + NE + e);
    }
    atomicAdd(&g_deg[dst], 1);
}

// ---------------- single-pass exclusive scan with spin-lookback ----------------
__global__ void k_scan() {
    __shared__ int wsum[8];
    __shared__ int red[8];
    __shared__ int s_off;
    int bid = blockIdx.x, t = threadIdx.x;
    int lane = t & 31, wid = t >> 5;
    int i = bid * 256 + t;
    int val = (i < NN) ? g_deg[i] : 0;
    int v = val;
    #pragma unroll
    for (int o = 1; o < 32; o <<= 1) {
        int u = __shfl_up_sync(0xffffffffu, v, o);
        if (lane >= o) v += u;
    }
    if (lane == 31) wsum[wid] = v;
    __syncthreads();
    if (wid == 0 && lane < 8) {
        int w = wsum[lane];
        #pragma unroll
        for (int o = 1; o < 8; o <<= 1) {
            int u = __shfl_up_sync(0xFFu, w, o, 8);
            if (lane >= o) w += u;
        }
        wsum[lane] = w;
    }
    __syncthreads();
    int excl = (v - val) + (wid ? wsum[wid - 1] : 0);
    if (t == 0) {
        g_bsum[bid] = wsum[7];
        __threadfence();
        atomicExch(&g_bflag[bid], 1);
    }
    int part = 0;
    for (int p = t; p < bid; p += 256) {
        while (atomicAdd(&g_bflag[p], 0) == 0) { }
        __threadfence();
        part += *((volatile int*)&g_bsum[p]);
    }
    #pragma unroll
    for (int o = 16; o; o >>= 1) part += __shfl_xor_sync(0xffffffffu, part, o);
    if (lane == 0) red[wid] = part;
    __syncthreads();
    if (t == 0) {
        int r = 0;
        #pragma unroll
        for (int j = 0; j < 8; j++) r += red[j];
        s_off = r;
    }
    __syncthreads();
    int rp = s_off + excl;
    if (i < NN) { g_rowptr[i] = rp; g_cursor[i] = rp; }
    if (i == 0) g_rowptr[NN] = NE;
}

// ---------------- scatter: lean, full occupancy ----------------
__global__ void __launch_bounds__(256) k_scatter(const int* __restrict__ ei,
                                                 const float* __restrict__ ew) {
    int e = blockIdx.x * 256 + threadIdx.x;   // exact: NE/256 blocks
    int src, dst;
    if (g_flag64) {
        src = (int)__ldcs((const long long*)ei + e);
        dst = (int)__ldcs((const long long*)ei + NE + e);
    } else {
        src = __ldcs(ei + e);
        dst = __ldcs(ei + NE + e);
    }
    int pos = atomicAdd(&g_cursor[dst], 1);
    g_csr[pos] = make_int2(src, __float_as_int(ew[e]));
}

// ---------------- gemm: t0 = x @ W1 (100000x512 @ 512x8), warp per 2 nodes ------
__global__ void __launch_bounds__(256) k_gemm(const float* __restrict__ x,
                                              const float* __restrict__ W1) {
    __shared__ float Wt[8 * 512];  // Wt[o*512+k] = W1[k*8+o]
    for (int idx = threadIdx.x; idx < 4096; idx += 256) {
        int o = idx >> 9, k = idx & 511;
        Wt[idx] = W1[k * 8 + o];
    }
    __syncthreads();
    int warp = (blockIdx.x * 256 + threadIdx.x) >> 5;
    int lane = threadIdx.x & 31;
    int nb = warp * 2;  // 50000 warps cover 100000 nodes

    float acc[2][8];
    #pragma unroll
    for (int i = 0; i < 2; i++)
        #pragma unroll
        for (int o = 0; o < 8; o++) acc[i][o] = 0.f;

    #pragma unroll
    for (int j = 0; j < 4; j++) {
        int c = 4 * lane + 128 * j;
        float4 xv0 = __ldcs((const float4*)(x + (size_t)nb * 512 + c));
        float4 xv1 = __ldcs((const float4*)(x + (size_t)(nb + 1) * 512 + c));
        #pragma unroll
        for (int o = 0; o < 8; o++) {
            float4 wv = *(const float4*)(Wt + o * 512 + c);
            acc[0][o] += xv0.x * wv.x + xv0.y * wv.y + xv0.z * wv.z + xv0.w * wv.w;
            acc[1][o] += xv1.x * wv.x + xv1.y * wv.y + xv1.z * wv.z + xv1.w * wv.w;
        }
    }
    float myval = 0.f;
    #pragma unroll
    for (int i = 0; i < 2; i++)
        #pragma unroll
        for (int o = 0; o < 8; o++) {
            float r = acc[i][o];
            #pragma unroll
            for (int off = 16; off; off >>= 1) r += __shfl_xor_sync(0xffffffffu, r, off);
            if (lane == i * 8 + o) myval = r;
        }
    if (lane < 16) g_t0[(size_t)nb * 8 + lane] = __float2half(myval);
}

// ================= gathers =======================================================
// fp16 8-wide table, group of 4 lanes, lane f holds features {2f, 2f+1} as half2.
#define GATHER_H8(TINH2)                                                         \
    int s = g_rowptr[gid], e = g_rowptr[gid + 1];                                \
    unsigned gmask = 0xFu << (threadIdx.x & 28);                                 \
    float acc0 = 0.f, acc1 = 0.f;                                                \
    int i = s;                                                                   \
    for (; i + 4 <= e; i += 4) {                                                 \
        int2 my = g_csr[i + f];                                                  \
        _Pragma("unroll")                                                        \
        for (int k = 0; k < 4; k++) {                                            \
            int   sk = __shfl_sync(gmask, my.x, k, 4);                           \
            float wk = __int_as_float(__shfl_sync(gmask, my.y, k, 4));           \
            float2 v = __half22float2(TINH2[(size_t)sk * 4 + f]);                \
            acc0 += v.x * wk;  acc1 += v.y * wk;                                 \
        }                                                                        \
    }                                                                            \
    int rem = e - i;                                                             \
    if (rem) {                                                                   \
        int2 my = make_int2(0, 0);                                               \
        if (f < rem) my = g_csr[i + f];                                          \
        _Pragma("unroll")                                                        \
        for (int k = 0; k < 3; k++) {                                            \
            int   sk = __shfl_sync(gmask, my.x, k, 4);                           \
            float wk = __int_as_float(__shfl_sync(gmask, my.y, k, 4));           \
            if (k < rem) {                                                       \
                float2 v = __half22float2(TINH2[(size_t)sk * 4 + f]);            \
                acc0 += v.x * wk;  acc1 += v.y * wk;                             \
            }                                                                    \
        }                                                                        \
    }

// fp16 16-wide table, group of 8 lanes, lane f holds features {2f, 2f+1} as half2.
#define GATHER_H16(TINH2)                                                        \
    int s = g_rowptr[gid], e = g_rowptr[gid + 1];                                \
    unsigned gmask = 0xFFu << (threadIdx.x & 24);                                \
    float acc0 = 0.f, acc1 = 0.f;                                                \
    int i = s;                                                                   \
    for (; i + 8 <= e; i += 8) {                                                 \
        int2 my = g_csr[i + f];                                                  \
        _Pragma("unroll")                                                        \
        for (int k = 0; k < 8; k++) {                                            \
            int   sk = __shfl_sync(gmask, my.x, k, 8);                           \
            float wk = __int_as_float(__shfl_sync(gmask, my.y, k, 8));           \
            float2 v = __half22float2(TINH2[(size_t)sk * 8 + f]);                \
            acc0 += v.x * wk;  acc1 += v.y * wk;                                 \
        }                                                                        \
    }                                                                            \
    int rem = e - i;                                                             \
    if (rem) {                                                                   \
        int2 my = make_int2(0, 0);                                               \
        if (f < rem) my = g_csr[i + f];                                          \
        _Pragma("unroll")                                                        \
        for (int k = 0; k < 7; k++) {                                            \
            int   sk = __shfl_sync(gmask, my.x, k, 8);                           \
            float wk = __int_as_float(__shfl_sync(gmask, my.y, k, 8));           \
            if (k < rem) {                                                       \
                float2 v = __half22float2(TINH2[(size_t)sk * 8 + f]);            \
                acc0 += v.x * wk;  acc1 += v.y * wk;                             \
            }                                                                    \
        }                                                                        \
    }

// ---------------- layer 1: agg(t0) + b1, relu, @W2 (8->16), store half ----------
__global__ void k_agg1(const float* __restrict__ b1, const float* __restrict__ W2) {
    __shared__ float Ws[8 * 16];
    __shared__ float bs[8];
    if (threadIdx.x < 128) Ws[threadIdx.x] = W2[threadIdx.x];
    if (threadIdx.x < 8) bs[threadIdx.x] = b1[threadIdx.x];
    __syncthreads();
    int t = blockIdx.x * 256 + threadIdx.x;
    int gid = t >> 2, f = t & 3;
    if (gid >= NN) return;
    GATHER_H8(((const __half2*)g_t0))
    float h0 = fmaxf(acc0 + bs[2 * f], 0.f);
    float h1 = fmaxf(acc1 + bs[2 * f + 1], 0.f);
    unsigned m2 = 0xFu << (threadIdx.x & 28);
    float o0 = 0.f, o1 = 0.f, o2 = 0.f, o3 = 0.f;
    #pragma unroll
    for (int j = 0; j < 4; j++) {
        float a0 = __shfl_sync(m2, h0, j, 4);
        float a1 = __shfl_sync(m2, h1, j, 4);
        o0 += a0 * Ws[(2 * j) * 16 + 2 * f]     + a1 * Ws[(2 * j + 1) * 16 + 2 * f];
        o1 += a0 * Ws[(2 * j) * 16 + 2 * f + 1] + a1 * Ws[(2 * j + 1) * 16 + 2 * f + 1];
        o2 += a0 * Ws[(2 * j) * 16 + 2 * f + 8] + a1 * Ws[(2 * j + 1) * 16 + 2 * f + 8];
        o3 += a0 * Ws[(2 * j) * 16 + 2 * f + 9] + a1 * Ws[(2 * j + 1) * 16 + 2 * f + 9];
    }
    __half2* H = (__half2*)g_h1;
    H[(size_t)gid * 8 + f]     = __floats2half2_rn(o0, o1);
    H[(size_t)gid * 8 + f + 4] = __floats2half2_rn(o2, o3);
}

// ---------------- layer 2: agg(h1) + b2, relu, @W3 (16->8), store half ----------
__global__ void k_agg2(const float* __restrict__ b2, const float* __restrict__ W3) {
    __shared__ float Ws[16 * 8];
    __shared__ float bs[16];
    if (threadIdx.x < 128) Ws[threadIdx.x] = W3[threadIdx.x];
    if (threadIdx.x < 16) bs[threadIdx.x] = b2[threadIdx.x];
    __syncthreads();
    int t = blockIdx.x * 256 + threadIdx.x;
    int gid = t >> 3, f = t & 7;
    GATHER_H16(((const __half2*)g_h1))
    float h0 = fmaxf(acc0 + bs[2 * f], 0.f);
    float h1 = fmaxf(acc1 + bs[2 * f + 1], 0.f);
    float out = 0.f;
    #pragma unroll
    for (int k = 0; k < 8; k++) {
        float hk0 = __shfl_sync(0xffffffffu, h0, k, 8);
        float hk1 = __shfl_sync(0xffffffffu, h1, k, 8);
        out += hk0 * Ws[(2 * k) * 8 + f] + hk1 * Ws[(2 * k + 1) * 8 + f];
    }
    g_t2[(size_t)gid * 8 + f] = __float2half(out);
}

// ---------------- layer 3: agg(t2) + b3, relu, @W4 (8->10 pad16), store half -----
__global__ void k_agg3(const float* __restrict__ b3, const float* __restrict__ W4) {
    __shared__ float Ws[8 * 16];
    __shared__ float bs[8];
    if (threadIdx.x < 128) {
        int k = threadIdx.x >> 4, o = threadIdx.x & 15;
        Ws[threadIdx.x] = (o < 10) ? W4[k * 10 + o] : 0.f;
    }
    if (threadIdx.x < 8) bs[threadIdx.x] = b3[threadIdx.x];
    __syncthreads();
    int t = blockIdx.x * 256 + threadIdx.x;
    int gid = t >> 2, f = t & 3;
    if (gid >= NN) return;
    GATHER_H8(((const __half2*)g_t2))
    float h0 = fmaxf(acc0 + bs[2 * f], 0.f);
    float h1 = fmaxf(acc1 + bs[2 * f + 1], 0.f);
    unsigned m2 = 0xFu << (threadIdx.x & 28);
    float o0 = 0.f, o1 = 0.f, o2 = 0.f, o3 = 0.f;
    #pragma unroll
    for (int j = 0; j < 4; j++) {
        float a0 = __shfl_sync(m2, h0, j, 4);
        float a1 = __shfl_sync(m2, h1, j, 4);
        o0 += a0 * Ws[(2 * j) * 16 + 2 * f]     + a1 * Ws[(2 * j + 1) * 16 + 2 * f];
        o1 += a0 * Ws[(2 * j) * 16 + 2 * f + 1] + a1 * Ws[(2 * j + 1) * 16 + 2 * f + 1];
        o2 += a0 * Ws[(2 * j) * 16 + 2 * f + 8] + a1 * Ws[(2 * j + 1) * 16 + 2 * f + 8];
        o3 += a0 * Ws[(2 * j) * 16 + 2 * f + 9] + a1 * Ws[(2 * j + 1) * 16 + 2 * f + 9];
    }
    __half2* H = (__half2*)g_h3;
    H[(size_t)gid * 8 + f]     = __floats2half2_rn(o0, o1);
    H[(size_t)gid * 8 + f + 4] = __floats2half2_rn(o2, o3);
}

// ---------------- layer 4: agg(h3) + b4, log_softmax over 10 classes ------------
__global__ void k_agg4(const float* __restrict__ b4, float* __restrict__ out) {
    __shared__ float bs[16];
    if (threadIdx.x < 16) bs[threadIdx.x] = (threadIdx.x < 10) ? b4[threadIdx.x] : 0.f;
    __syncthreads();
    int t = blockIdx.x * 256 + threadIdx.x;
    int gid = t >> 3, f = t & 7;
    GATHER_H16(((const __half2*)g_h3))
    float v0 = acc0 + bs[2 * f];
    float v1 = acc1 + bs[2 * f + 1];
    bool k0 = (2 * f) < 10, k1 = (2 * f + 1) < 10;
    float m = -INFINITY;
    if (k0) m = v0;
    if (k1) m = fmaxf(m, v1);
    #pragma unroll
    for (int off = 4; off; off >>= 1) m = fmaxf(m, __shfl_xor_sync(0xffffffffu, m, off, 8));
    float e0 = k0 ? expf(v0 - m) : 0.f;
    float e1 = k1 ? expf(v1 - m) : 0.f;
    float se = e0 + e1;
    #pragma unroll
    for (int off = 4; off; off >>= 1) se += __shfl_xor_sync(0xffffffffu, se, off, 8);
    float ls = logf(se);
    if (k0) out[(size_t)gid * 10 + 2 * f]     = v0 - m - ls;
    if (k1) out[(size_t)gid * 10 + 2 * f + 1] = v1 - m - ls;
}

// ---------------- launch ----------------
extern "C" void kernel_launch(void* const* d_in, const int* in_sizes, int n_in,
                              void* d_out, int out_size) {
    const float* x  = (const float*)d_in[0];
    const int*   ei = (const int*)d_in[1];
    const float* ew = (const float*)d_in[2];
    const float* W1 = (const float*)d_in[3];
    const float* b1 = (const float*)d_in[4];
    const float* W2 = (const float*)d_in[5];
    const float* b2 = (const float*)d_in[6];
    const float* W3 = (const float*)d_in[7];
    const float* b3 = (const float*)d_in[8];
    const float* W4 = (const float*)d_in[9];
    const float* b4 = (const float*)d_in[10];
    float* out = (float*)d_out;

    k_init<<<NBLK, 256>>>(ei);                    // 1
    k_count<<<NE / 256, 256>>>(ei);               // 2
    k_scan<<<NBLK, 256>>>();                      // 3
    k_scatter<<<NE / 256, 256>>>(ei, ew);         // 4  <- profiled next round
    k_gemm<<<6250, 256>>>(x, W1);                 // 5

    k_agg1<<<(NN * 4 + 255) / 256, 256>>>(b1, W2);     // 6
    k_agg2<<<NN * 8 / 256, 256>>>(b2, W3);             // 7
    k_agg3<<<(NN * 4 + 255) / 256, 256>>>(b3, W4);     // 8
    k_agg4<<<NN * 8 / 256, 256>>>(b4, out);            // 9
}

// round 13
// speedup vs baseline: 1.2359x; 1.1140x over previous
#include <cuda_runtime.h>
#include <cuda_fp16.h>
#include <math.h>

#define NN 100000
#define NE 3200000
#define NBLK 391            // ceil(NN/256)
#define CAP 128             // bucket capacity (Poisson(32) tail @128 ~ 1e-40/node)

// ---------------- device scratch ----------------
__device__ int    g_flag64;
__device__ int    g_deg[NN];
__device__ int2   g_csr[(size_t)NN * CAP];  // padded buckets: {src, weight-bits}
__device__ __half g_t0[NN * 8];        // x@W1                     (fp16, 8-wide)
__device__ __half g_h1[NN * 16];       // relu(agg1+b1)@W2         (fp16, 16-wide)
__device__ __half g_t2[NN * 8];        // relu(agg2+b2)@W3         (fp16, 8-wide)
__device__ __half g_h3[NN * 16];       // relu(agg3+b3)@W4 pad16   (fp16, 16-wide)

// ---------------- init: zero deg, detect int64 vs int32 ----------------
__global__ void k_init(const int* __restrict__ ei) {
    int i = blockIdx.x * 256 + threadIdx.x;
    if (i < NN) g_deg[i] = 0;
    if (blockIdx.x == 0 && threadIdx.x < 32) {
        int v = 0;
        for (int j = threadIdx.x; j < 512; j += 32) v |= ei[2 * j + 1];
        for (int o = 16; o; o >>= 1) v |= __shfl_xor_sync(0xffffffffu, v, o);
        if (threadIdx.x == 0) g_flag64 = (v == 0) ? 1 : 0;
    }
}

// ---------------- scatter+count: 4 edges/thread, padded buckets ----------------
__global__ void __launch_bounds__(256) k_scatter(const int* __restrict__ ei,
                                                 const float* __restrict__ ew) {
    int base = (blockIdx.x * 256 + threadIdx.x) * 4;   // exact: NE/(256*4) blocks
    int src[4], dst[4];
    if (g_flag64) {
        const longlong2* s2 = (const longlong2*)((const long long*)ei + base);
        const longlong2* d2 = (const longlong2*)((const long long*)ei + NE + base);
        longlong2 sa = __ldcs(s2), sb = __ldcs(s2 + 1);
        longlong2 da = __ldcs(d2), db = __ldcs(d2 + 1);
        src[0] = (int)sa.x; src[1] = (int)sa.y; src[2] = (int)sb.x; src[3] = (int)sb.y;
        dst[0] = (int)da.x; dst[1] = (int)da.y; dst[2] = (int)db.x; dst[3] = (int)db.y;
    } else {
        int4 s = __ldcs((const int4*)(ei + base));
        int4 d = __ldcs((const int4*)(ei + NE + base));
        src[0] = s.x; src[1] = s.y; src[2] = s.z; src[3] = s.w;
        dst[0] = d.x; dst[1] = d.y; dst[2] = d.z; dst[3] = d.w;
    }
    float4 w = __ldcs((const float4*)(ew + base));
    float wv[4] = {w.x, w.y, w.z, w.w};
    int pos[4];
    #pragma unroll
    for (int k = 0; k < 4; k++) pos[k] = atomicAdd(&g_deg[dst[k]], 1);
    #pragma unroll
    for (int k = 0; k < 4; k++)
        g_csr[(size_t)dst[k] * CAP + pos[k]] = make_int2(src[k], __float_as_int(wv[k]));
}

// ---------------- gemm: t0 = x @ W1 (100000x512 @ 512x8), warp per 2 nodes ------
__global__ void __launch_bounds__(256) k_gemm(const float* __restrict__ x,
                                              const float* __restrict__ W1) {
    __shared__ float Wt[8 * 512];  // Wt[o*512+k] = W1[k*8+o]
    for (int idx = threadIdx.x; idx < 4096; idx += 256) {
        int o = idx >> 9, k = idx & 511;
        Wt[idx] = W1[k * 8 + o];
    }
    __syncthreads();
    int warp = (blockIdx.x * 256 + threadIdx.x) >> 5;
    int lane = threadIdx.x & 31;
    int nb = warp * 2;  // 50000 warps cover 100000 nodes

    float acc[2][8];
    #pragma unroll
    for (int i = 0; i < 2; i++)
        #pragma unroll
        for (int o = 0; o < 8; o++) acc[i][o] = 0.f;

    #pragma unroll
    for (int j = 0; j < 4; j++) {
        int c = 4 * lane + 128 * j;
        float4 xv0 = __ldcs((const float4*)(x + (size_t)nb * 512 + c));
        float4 xv1 = __ldcs((const float4*)(x + (size_t)(nb + 1) * 512 + c));
        #pragma unroll
        for (int o = 0; o < 8; o++) {
            float4 wv = *(const float4*)(Wt + o * 512 + c);
            acc[0][o] += xv0.x * wv.x + xv0.y * wv.y + xv0.z * wv.z + xv0.w * wv.w;
            acc[1][o] += xv1.x * wv.x + xv1.y * wv.y + xv1.z * wv.z + xv1.w * wv.w;
        }
    }
    float myval = 0.f;
    #pragma unroll
    for (int i = 0; i < 2; i++)
        #pragma unroll
        for (int o = 0; o < 8; o++) {
            float r = acc[i][o];
            #pragma unroll
            for (int off = 16; off; off >>= 1) r += __shfl_xor_sync(0xffffffffu, r, off);
            if (lane == i * 8 + o) myval = r;
        }
    if (lane < 16) g_t0[(size_t)nb * 8 + lane] = __float2half(myval);
}

// ================= gathers (padded buckets: [gid*CAP, gid*CAP+deg)) ==============
// fp16 8-wide table, group of 4 lanes, lane f holds features {2f, 2f+1} as half2.
#define GATHER_H8(TINH2)                                                         \
    size_t s = (size_t)gid * CAP;                                                \
    int deg = g_deg[gid];                                                        \
    unsigned gmask = 0xFu << (threadIdx.x & 28);                                 \
    float acc0 = 0.f, acc1 = 0.f;                                                \
    int i = 0;                                                                   \
    for (; i + 4 <= deg; i += 4) {                                               \
        int2 my = g_csr[s + i + f];                                              \
        _Pragma("unroll")                                                        \
        for (int k = 0; k < 4; k++) {                                            \
            int   sk = __shfl_sync(gmask, my.x, k, 4);                           \
            float wk = __int_as_float(__shfl_sync(gmask, my.y, k, 4));           \
            float2 v = __half22float2(TINH2[(size_t)sk * 4 + f]);                \
            acc0 += v.x * wk;  acc1 += v.y * wk;                                 \
        }                                                                        \
    }                                                                            \
    int rem = deg - i;                                                           \
    if (rem) {                                                                   \
        int2 my = make_int2(0, 0);                                               \
        if (f < rem) my = g_csr[s + i + f];                                      \
        _Pragma("unroll")                                                        \
        for (int k = 0; k < 3; k++) {                                            \
            int   sk = __shfl_sync(gmask, my.x, k, 4);                           \
            float wk = __int_as_float(__shfl_sync(gmask, my.y, k, 4));           \
            if (k < rem) {                                                       \
                float2 v = __half22float2(TINH2[(size_t)sk * 4 + f]);            \
                acc0 += v.x * wk;  acc1 += v.y * wk;                             \
            }                                                                    \
        }                                                                        \
    }

// fp16 16-wide table, group of 8 lanes, lane f holds features {2f, 2f+1} as half2.
#define GATHER_H16(TINH2)                                                        \
    size_t s = (size_t)gid * CAP;                                                \
    int deg = g_deg[gid];                                                        \
    unsigned gmask = 0xFFu << (threadIdx.x & 24);                                \
    float acc0 = 0.f, acc1 = 0.f;                                                \
    int i = 0;                                                                   \
    for (; i + 8 <= deg; i += 8) {                                               \
        int2 my = g_csr[s + i + f];                                              \
        _Pragma("unroll")                                                        \
        for (int k = 0; k < 8; k++) {                                            \
            int   sk = __shfl_sync(gmask, my.x, k, 8);                           \
            float wk = __int_as_float(__shfl_sync(gmask, my.y, k, 8));           \
            float2 v = __half22float2(TINH2[(size_t)sk * 8 + f]);                \
            acc0 += v.x * wk;  acc1 += v.y * wk;                                 \
        }                                                                        \
    }                                                                            \
    int rem = deg - i;                                                           \
    if (rem) {                                                                   \
        int2 my = make_int2(0, 0);                                               \
        if (f < rem) my = g_csr[s + i + f];                                      \
        _Pragma("unroll")                                                        \
        for (int k = 0; k < 7; k++) {                                            \
            int   sk = __shfl_sync(gmask, my.x, k, 8);                           \
            float wk = __int_as_float(__shfl_sync(gmask, my.y, k, 8));           \
            if (k < rem) {                                                       \
                float2 v = __half22float2(TINH2[(size_t)sk * 8 + f]);            \
                acc0 += v.x * wk;  acc1 += v.y * wk;                             \
            }                                                                    \
        }                                                                        \
    }

// ---------------- layer 1: agg(t0) + b1, relu, @W2 (8->16), store half ----------
__global__ void k_agg1(const float* __restrict__ b1, const float* __restrict__ W2) {
    __shared__ float Ws[8 * 16];
    __shared__ float bs[8];
    if (threadIdx.x < 128) Ws[threadIdx.x] = W2[threadIdx.x];
    if (threadIdx.x < 8) bs[threadIdx.x] = b1[threadIdx.x];
    __syncthreads();
    int t = blockIdx.x * 256 + threadIdx.x;
    int gid = t >> 2, f = t & 3;
    if (gid >= NN) return;
    GATHER_H8(((const __half2*)g_t0))
    float h0 = fmaxf(acc0 + bs[2 * f], 0.f);
    float h1 = fmaxf(acc1 + bs[2 * f + 1], 0.f);
    unsigned m2 = 0xFu << (threadIdx.x & 28);
    float o0 = 0.f, o1 = 0.f, o2 = 0.f, o3 = 0.f;
    #pragma unroll
    for (int j = 0; j < 4; j++) {
        float a0 = __shfl_sync(m2, h0, j, 4);
        float a1 = __shfl_sync(m2, h1, j, 4);
        o0 += a0 * Ws[(2 * j) * 16 + 2 * f]     + a1 * Ws[(2 * j + 1) * 16 + 2 * f];
        o1 += a0 * Ws[(2 * j) * 16 + 2 * f + 1] + a1 * Ws[(2 * j + 1) * 16 + 2 * f + 1];
        o2 += a0 * Ws[(2 * j) * 16 + 2 * f + 8] + a1 * Ws[(2 * j + 1) * 16 + 2 * f + 8];
        o3 += a0 * Ws[(2 * j) * 16 + 2 * f + 9] + a1 * Ws[(2 * j + 1) * 16 + 2 * f + 9];
    }
    __half2* H = (__half2*)g_h1;
    H[(size_t)gid * 8 + f]     = __floats2half2_rn(o0, o1);
    H[(size_t)gid * 8 + f + 4] = __floats2half2_rn(o2, o3);
}

// ---------------- layer 2: agg(h1) + b2, relu, @W3 (16->8), store half ----------
__global__ void k_agg2(const float* __restrict__ b2, const float* __restrict__ W3) {
    __shared__ float Ws[16 * 8];
    __shared__ float bs[16];
    if (threadIdx.x < 128) Ws[threadIdx.x] = W3[threadIdx.x];
    if (threadIdx.x < 16) bs[threadIdx.x] = b2[threadIdx.x];
    __syncthreads();
    int t = blockIdx.x * 256 + threadIdx.x;
    int gid = t >> 3, f = t & 7;
    GATHER_H16(((const __half2*)g_h1))
    float h0 = fmaxf(acc0 + bs[2 * f], 0.f);
    float h1 = fmaxf(acc1 + bs[2 * f + 1], 0.f);
    float out = 0.f;
    #pragma unroll
    for (int k = 0; k < 8; k++) {
        float hk0 = __shfl_sync(0xffffffffu, h0, k, 8);
        float hk1 = __shfl_sync(0xffffffffu, h1, k, 8);
        out += hk0 * Ws[(2 * k) * 8 + f] + hk1 * Ws[(2 * k + 1) * 8 + f];
    }
    g_t2[(size_t)gid * 8 + f] = __float2half(out);
}

// ---------------- layer 3: agg(t2) + b3, relu, @W4 (8->10 pad16), store half -----
__global__ void k_agg3(const float* __restrict__ b3, const float* __restrict__ W4) {
    __shared__ float Ws[8 * 16];
    __shared__ float bs[8];
    if (threadIdx.x < 128) {
        int k = threadIdx.x >> 4, o = threadIdx.x & 15;
        Ws[threadIdx.x] = (o < 10) ? W4[k * 10 + o] : 0.f;
    }
    if (threadIdx.x < 8) bs[threadIdx.x] = b3[threadIdx.x];
    __syncthreads();
    int t = blockIdx.x * 256 + threadIdx.x;
    int gid = t >> 2, f = t & 3;
    if (gid >= NN) return;
    GATHER_H8(((const __half2*)g_t2))
    float h0 = fmaxf(acc0 + bs[2 * f], 0.f);
    float h1 = fmaxf(acc1 + bs[2 * f + 1], 0.f);
    unsigned m2 = 0xFu << (threadIdx.x & 28);
    float o0 = 0.f, o1 = 0.f, o2 = 0.f, o3 = 0.f;
    #pragma unroll
    for (int j = 0; j < 4; j++) {
        float a0 = __shfl_sync(m2, h0, j, 4);
        float a1 = __shfl_sync(m2, h1, j, 4);
        o0 += a0 * Ws[(2 * j) * 16 + 2 * f]     + a1 * Ws[(2 * j + 1) * 16 + 2 * f];
        o1 += a0 * Ws[(2 * j) * 16 + 2 * f + 1] + a1 * Ws[(2 * j + 1) * 16 + 2 * f + 1];
        o2 += a0 * Ws[(2 * j) * 16 + 2 * f + 8] + a1 * Ws[(2 * j + 1) * 16 + 2 * f + 8];
        o3 += a0 * Ws[(2 * j) * 16 + 2 * f + 9] + a1 * Ws[(2 * j + 1) * 16 + 2 * f + 9];
    }
    __half2* H = (__half2*)g_h3;
    H[(size_t)gid * 8 + f]     = __floats2half2_rn(o0, o1);
    H[(size_t)gid * 8 + f + 4] = __floats2half2_rn(o2, o3);
}

// ---------------- layer 4: agg(h3) + b4, log_softmax over 10 classes ------------
__global__ void k_agg4(const float* __restrict__ b4, float* __restrict__ out) {
    __shared__ float bs[16];
    if (threadIdx.x < 16) bs[threadIdx.x] = (threadIdx.x < 10) ? b4[threadIdx.x] : 0.f;
    __syncthreads();
    int t = blockIdx.x * 256 + threadIdx.x;
    int gid = t >> 3, f = t & 7;
    GATHER_H16(((const __half2*)g_h3))
    float v0 = acc0 + bs[2 * f];
    float v1 = acc1 + bs[2 * f + 1];
    bool k0 = (2 * f) < 10, k1 = (2 * f + 1) < 10;
    float m = -INFINITY;
    if (k0) m = v0;
    if (k1) m = fmaxf(m, v1);
    #pragma unroll
    for (int off = 4; off; off >>= 1) m = fmaxf(m, __shfl_xor_sync(0xffffffffu, m, off, 8));
    float e0 = k0 ? expf(v0 - m) : 0.f;
    float e1 = k1 ? expf(v1 - m) : 0.f;
    float se = e0 + e1;
    #pragma unroll
    for (int off = 4; off; off >>= 1) se += __shfl_xor_sync(0xffffffffu, se, off, 8);
    float ls = logf(se);
    if (k0) out[(size_t)gid * 10 + 2 * f]     = v0 - m - ls;
    if (k1) out[(size_t)gid * 10 + 2 * f + 1] = v1 - m - ls;
}

// ---------------- launch ----------------
extern "C" void kernel_launch(void* const* d_in, const int* in_sizes, int n_in,
                              void* d_out, int out_size) {
    const float* x  = (const float*)d_in[0];
    const int*   ei = (const int*)d_in[1];
    const float* ew = (const float*)d_in[2];
    const float* W1 = (const float*)d_in[3];
    const float* b1 = (const float*)d_in[4];
    const float* W2 = (const float*)d_in[5];
    const float* b2 = (const float*)d_in[6];
    const float* W3 = (const float*)d_in[7];
    const float* b3 = (const float*)d_in[8];
    const float* W4 = (const float*)d_in[9];
    const float* b4 = (const float*)d_in[10];
    float* out = (float*)d_out;

    k_init<<<NBLK, 256>>>(ei);                     // 1
    k_scatter<<<NE / 1024, 256>>>(ei, ew);         // 2  (count+scatter fused)
    k_gemm<<<6250, 256>>>(x, W1);                  // 3

    k_agg1<<<(NN * 4 + 255) / 256, 256>>>(b1, W2); // 4  <- profiled next round
    k_agg2<<<NN * 8 / 256, 256>>>(b2, W3);         // 5
    k_agg3<<<(NN * 4 + 255) / 256, 256>>>(b3, W4); // 6
    k_agg4<<<NN * 8 / 256, 256>>>(b4, out);        // 7
}

// round 15
// speedup vs baseline: 1.2427x; 1.0055x over previous
#include <cuda_runtime.h>
#include <cuda_fp16.h>
#include <math.h>

#define NN 100000
#define NE 3200000
#define NBLK 391            // ceil(NN/256)
#define CAP 128             // bucket capacity (Poisson(32) tail @128 ~ 1e-40/node)

// ---------------- device scratch ----------------
__device__ int    g_flag64;
__device__ int    g_deg[NN];
__device__ int2   g_csr[(size_t)NN * CAP];  // padded buckets: {src, weight-bits}
__device__ __half g_t0[NN * 8];        // x@W1                     (fp16, 8-wide)
__device__ __half g_h1[NN * 16];       // relu(agg1+b1)@W2         (fp16, 16-wide)
__device__ __half g_t2[NN * 8];        // relu(agg2+b2)@W3         (fp16, 8-wide)
__device__ __half g_h3[NN * 16];       // relu(agg3+b3)@W4 pad16   (fp16, 16-wide)

// ---------------- init: zero deg, detect int64 vs int32 ----------------
__global__ void k_init(const int* __restrict__ ei) {
    int i = blockIdx.x * 256 + threadIdx.x;
    if (i < NN) g_deg[i] = 0;
    if (blockIdx.x == 0 && threadIdx.x < 32) {
        int v = 0;
        for (int j = threadIdx.x; j < 512; j += 32) v |= ei[2 * j + 1];
        for (int o = 16; o; o >>= 1) v |= __shfl_xor_sync(0xffffffffu, v, o);
        if (threadIdx.x == 0) g_flag64 = (v == 0) ? 1 : 0;
    }
}

// ---------------- scatter+count: 4 edges/thread, padded buckets ----------------
__global__ void __launch_bounds__(256) k_scatter(const int* __restrict__ ei,
                                                 const float* __restrict__ ew) {
    int base = (blockIdx.x * 256 + threadIdx.x) * 4;   // exact: NE/(256*4) blocks
    int src[4], dst[4];
    if (g_flag64) {
        const longlong2* s2 = (const longlong2*)((const long long*)ei + base);
        const longlong2* d2 = (const longlong2*)((const long long*)ei + NE + base);
        longlong2 sa = __ldcs(s2), sb = __ldcs(s2 + 1);
        longlong2 da = __ldcs(d2), db = __ldcs(d2 + 1);
        src[0] = (int)sa.x; src[1] = (int)sa.y; src[2] = (int)sb.x; src[3] = (int)sb.y;
        dst[0] = (int)da.x; dst[1] = (int)da.y; dst[2] = (int)db.x; dst[3] = (int)db.y;
    } else {
        int4 s = __ldcs((const int4*)(ei + base));
        int4 d = __ldcs((const int4*)(ei + NE + base));
        src[0] = s.x; src[1] = s.y; src[2] = s.z; src[3] = s.w;
        dst[0] = d.x; dst[1] = d.y; dst[2] = d.z; dst[3] = d.w;
    }
    float4 w = __ldcs((const float4*)(ew + base));
    float wv[4] = {w.x, w.y, w.z, w.w};
    int pos[4];
    #pragma unroll
    for (int k = 0; k < 4; k++) pos[k] = atomicAdd(&g_deg[dst[k]], 1);
    #pragma unroll
    for (int k = 0; k < 4; k++)
        g_csr[(size_t)dst[k] * CAP + pos[k]] = make_int2(src[k], __float_as_int(wv[k]));
}

// ---------------- gemm: t0 = x @ W1 (100000x512 @ 512x8), warp per 2 nodes ------
__global__ void __launch_bounds__(256) k_gemm(const float* __restrict__ x,
                                              const float* __restrict__ W1) {
    __shared__ float Wt[8 * 512];  // Wt[o*512+k] = W1[k*8+o]
    for (int idx = threadIdx.x; idx < 4096; idx += 256) {
        int o = idx >> 9, k = idx & 511;
        Wt[idx] = W1[k * 8 + o];
    }
    __syncthreads();
    int warp = (blockIdx.x * 256 + threadIdx.x) >> 5;
    int lane = threadIdx.x & 31;
    int nb = warp * 2;  // 50000 warps cover 100000 nodes

    float acc[2][8];
    #pragma unroll
    for (int i = 0; i < 2; i++)
        #pragma unroll
        for (int o = 0; o < 8; o++) acc[i][o] = 0.f;

    #pragma unroll
    for (int j = 0; j < 4; j++) {
        int c = 4 * lane + 128 * j;
        float4 xv0 = __ldcs((const float4*)(x + (size_t)nb * 512 + c));
        float4 xv1 = __ldcs((const float4*)(x + (size_t)(nb + 1) * 512 + c));
        #pragma unroll
        for (int o = 0; o < 8; o++) {
            float4 wv = *(const float4*)(Wt + o * 512 + c);
            acc[0][o] += xv0.x * wv.x + xv0.y * wv.y + xv0.z * wv.z + xv0.w * wv.w;
            acc[1][o] += xv1.x * wv.x + xv1.y * wv.y + xv1.z * wv.z + xv1.w * wv.w;
        }
    }
    float myval = 0.f;
    #pragma unroll
    for (int i = 0; i < 2; i++)
        #pragma unroll
        for (int o = 0; o < 8; o++) {
            float r = acc[i][o];
            #pragma unroll
            for (int off = 16; off; off >>= 1) r += __shfl_xor_sync(0xffffffffu, r, off);
            if (lane == i * 8 + o) myval = r;
        }
    if (lane < 16) g_t0[(size_t)nb * 8 + lane] = __float2half(myval);
}

// ================= gathers (padded buckets: [gid*CAP, gid*CAP+deg)) ==============
// fp16 8-wide table, group of 4 lanes, lane f holds features {2f, 2f+1} as half2.
#define GATHER_H8(TINH2)                                                         \
    size_t s = (size_t)gid * CAP;                                                \
    int deg = g_deg[gid];                                                        \
    unsigned gmask = 0xFu << (threadIdx.x & 28);                                 \
    float acc0 = 0.f, acc1 = 0.f;                                                \
    int i = 0;                                                                   \
    for (; i + 4 <= deg; i += 4) {                                               \
        int2 my = g_csr[s + i + f];                                              \
        _Pragma("unroll")                                                        \
        for (int k = 0; k < 4; k++) {                                            \
            int   sk = __shfl_sync(gmask, my.x, k, 4);                           \
            float wk = __int_as_float(__shfl_sync(gmask, my.y, k, 4));           \
            float2 v = __half22float2(TINH2[(size_t)sk * 4 + f]);                \
            acc0 += v.x * wk;  acc1 += v.y * wk;                                 \
        }                                                                        \
    }                                                                            \
    int rem = deg - i;                                                           \
    if (rem) {                                                                   \
        int2 my = make_int2(0, 0);                                               \
        if (f < rem) my = g_csr[s + i + f];                                      \
        _Pragma("unroll")                                                        \
        for (int k = 0; k < 3; k++) {                                            \
            int   sk = __shfl_sync(gmask, my.x, k, 4);                           \
            float wk = __int_as_float(__shfl_sync(gmask, my.y, k, 4));           \
            if (k < rem) {                                                       \
                float2 v = __half22float2(TINH2[(size_t)sk * 4 + f]);            \
                acc0 += v.x * wk;  acc1 += v.y * wk;                             \
            }                                                                    \
        }                                                                        \
    }

// fp16 16-wide table, group of 8 lanes, lane f holds features {2f, 2f+1} as half2.
#define GATHER_H16(TINH2)                                                        \
    size_t s = (size_t)gid * CAP;                                                \
    int deg = g_deg[gid];                                                        \
    unsigned gmask = 0xFFu << (threadIdx.x & 24);                                \
    float acc0 = 0.f, acc1 = 0.f;                                                \
    int i = 0;                                                                   \
    for (; i + 8 <= deg; i += 8) {                                               \
        int2 my = g_csr[s + i + f];                                              \
        _Pragma("unroll")                                                        \
        for (int k = 0; k < 8; k++) {                                            \
            int   sk = __shfl_sync(gmask, my.x, k, 8);                           \
            float wk = __int_as_float(__shfl_sync(gmask, my.y, k, 8));           \
            float2 v = __half22float2(TINH2[(size_t)sk * 8 + f]);                \
            acc0 += v.x * wk;  acc1 += v.y * wk;                                 \
        }                                                                        \
    }                                                                            \
    int rem = deg - i;                                                           \
    if (rem) {                                                                   \
        int2 my = make_int2(0, 0);                                               \
        if (f < rem) my = g_csr[s + i + f];                                      \
        _Pragma("unroll")                                                        \
        for (int k = 0; k < 7; k++) {                                            \
            int   sk = __shfl_sync(gmask, my.x, k, 8);                           \
            float wk = __int_as_float(__shfl_sync(gmask, my.y, k, 8));           \
            if (k < rem) {                                                       \
                float2 v = __half22float2(TINH2[(size_t)sk * 8 + f]);            \
                acc0 += v.x * wk;  acc1 += v.y * wk;                             \
            }                                                                    \
        }                                                                        \
    }

// ---------------- layer 1: agg(t0) + b1, relu, @W2 (8->16), store half ----------
__global__ void k_agg1(const float* __restrict__ b1, const float* __restrict__ W2) {
    __shared__ float Ws[8 * 16];
    __shared__ float bs[8];
    if (threadIdx.x < 128) Ws[threadIdx.x] = W2[threadIdx.x];
    if (threadIdx.x < 8) bs[threadIdx.x] = b1[threadIdx.x];
    __syncthreads();
    int t = blockIdx.x * 256 + threadIdx.x;
    int gid = t >> 2, f = t & 3;
    if (gid >= NN) return;
    GATHER_H8(((const __half2*)g_t0))
    float h0 = fmaxf(acc0 + bs[2 * f], 0.f);
    float h1 = fmaxf(acc1 + bs[2 * f + 1], 0.f);
    unsigned m2 = 0xFu << (threadIdx.x & 28);
    float o0 = 0.f, o1 = 0.f, o2 = 0.f, o3 = 0.f;
    #pragma unroll
    for (int j = 0; j < 4; j++) {
        float a0 = __shfl_sync(m2, h0, j, 4);
        float a1 = __shfl_sync(m2, h1, j, 4);
        o0 += a0 * Ws[(2 * j) * 16 + 2 * f]     + a1 * Ws[(2 * j + 1) * 16 + 2 * f];
        o1 += a0 * Ws[(2 * j) * 16 + 2 * f + 1] + a1 * Ws[(2 * j + 1) * 16 + 2 * f + 1];
        o2 += a0 * Ws[(2 * j) * 16 + 2 * f + 8] + a1 * Ws[(2 * j + 1) * 16 + 2 * f + 8];
        o3 += a0 * Ws[(2 * j) * 16 + 2 * f + 9] + a1 * Ws[(2 * j + 1) * 16 + 2 * f + 9];
    }
    __half2* H = (__half2*)g_h1;
    H[(size_t)gid * 8 + f]     = __floats2half2_rn(o0, o1);
    H[(size_t)gid * 8 + f + 4] = __floats2half2_rn(o2, o3);
}

// ---------------- layer 2: agg(h1) + b2, relu, @W3 (16->8), store half ----------
__global__ void k_agg2(const float* __restrict__ b2, const float* __restrict__ W3) {
    __shared__ float Ws[16 * 8];
    __shared__ float bs[16];
    if (threadIdx.x < 128) Ws[threadIdx.x] = W3[threadIdx.x];
    if (threadIdx.x < 16) bs[threadIdx.x] = b2[threadIdx.x];
    __syncthreads();
    int t = blockIdx.x * 256 + threadIdx.x;
    int gid = t >> 3, f = t & 7;
    GATHER_H16(((const __half2*)g_h1))
    float h0 = fmaxf(acc0 + bs[2 * f], 0.f);
    float h1 = fmaxf(acc1 + bs[2 * f + 1], 0.f);
    float out = 0.f;
    #pragma unroll
    for (int k = 0; k < 8; k++) {
        float hk0 = __shfl_sync(0xffffffffu, h0, k, 8);
        float hk1 = __shfl_sync(0xffffffffu, h1, k, 8);
        out += hk0 * Ws[(2 * k) * 8 + f] + hk1 * Ws[(2 * k + 1) * 8 + f];
    }
    g_t2[(size_t)gid * 8 + f] = __float2half(out);
}

// ---------------- layer 3: agg(t2) + b3, relu, @W4 (8->10 pad16), store half -----
__global__ void k_agg3(const float* __restrict__ b3, const float* __restrict__ W4) {
    __shared__ float Ws[8 * 16];
    __shared__ float bs[8];
    if (threadIdx.x < 128) {
        int k = threadIdx.x >> 4, o = threadIdx.x & 15;
        Ws[threadIdx.x] = (o < 10) ? W4[k * 10 + o] : 0.f;
    }
    if (threadIdx.x < 8) bs[threadIdx.x] = b3[threadIdx.x];
    __syncthreads();
    int t = blockIdx.x * 256 + threadIdx.x;
    int gid = t >> 2, f = t & 3;
    if (gid >= NN) return;
    GATHER_H8(((const __half2*)g_t2))
    float h0 = fmaxf(acc0 + bs[2 * f], 0.f);
    float h1 = fmaxf(acc1 + bs[2 * f + 1], 0.f);
    unsigned m2 = 0xFu << (threadIdx.x & 28);
    float o0 = 0.f, o1 = 0.f, o2 = 0.f, o3 = 0.f;
    #pragma unroll
    for (int j = 0; j < 4; j++) {
        float a0 = __shfl_sync(m2, h0, j, 4);
        float a1 = __shfl_sync(m2, h1, j, 4);
        o0 += a0 * Ws[(2 * j) * 16 + 2 * f]     + a1 * Ws[(2 * j + 1) * 16 + 2 * f];
        o1 += a0 * Ws[(2 * j) * 16 + 2 * f + 1] + a1 * Ws[(2 * j + 1) * 16 + 2 * f + 1];
        o2 += a0 * Ws[(2 * j) * 16 + 2 * f + 8] + a1 * Ws[(2 * j + 1) * 16 + 2 * f + 8];
        o3 += a0 * Ws[(2 * j) * 16 + 2 * f + 9] + a1 * Ws[(2 * j + 1) * 16 + 2 * f + 9];
    }
    __half2* H = (__half2*)g_h3;
    H[(size_t)gid * 8 + f]     = __floats2half2_rn(o0, o1);
    H[(size_t)gid * 8 + f + 4] = __floats2half2_rn(o2, o3);
}

// ---------------- layer 4: agg(h3) + b4, log_softmax over 10 classes ------------
__global__ void k_agg4(const float* __restrict__ b4, float* __restrict__ out) {
    __shared__ float bs[16];
    if (threadIdx.x < 16) bs[threadIdx.x] = (threadIdx.x < 10) ? b4[threadIdx.x] : 0.f;
    __syncthreads();
    int t = blockIdx.x * 256 + threadIdx.x;
    int gid = t >> 3, f = t & 7;
    GATHER_H16(((const __half2*)g_h3))
    float v0 = acc0 + bs[2 * f];
    float v1 = acc1 + bs[2 * f + 1];
    bool k0 = (2 * f) < 10, k1 = (2 * f + 1) < 10;
    float m = -INFINITY;
    if (k0) m = v0;
    if (k1) m = fmaxf(m, v1);
    #pragma unroll
    for (int off = 4; off; off >>= 1) m = fmaxf(m, __shfl_xor_sync(0xffffffffu, m, off, 8));
    float e0 = k0 ? expf(v0 - m) : 0.f;
    float e1 = k1 ? expf(v1 - m) : 0.f;
    float se = e0 + e1;
    #pragma unroll
    for (int off = 4; off; off >>= 1) se += __shfl_xor_sync(0xffffffffu, se, off, 8);
    float ls = logf(se);
    if (k0) out[(size_t)gid * 10 + 2 * f]     = v0 - m - ls;
    if (k1) out[(size_t)gid * 10 + 2 * f + 1] = v1 - m - ls;
}

// ---------------- launch: fork-join overlap of gemm with CSR build ----------------
extern "C" void kernel_launch(void* const* d_in, const int* in_sizes, int n_in,
                              void* d_out, int out_size) {
    const float* x  = (const float*)d_in[0];
    const int*   ei = (const int*)d_in[1];
    const float* ew = (const float*)d_in[2];
    const float* W1 = (const float*)d_in[3];
    const float* b1 = (const float*)d_in[4];
    const float* W2 = (const float*)d_in[5];
    const float* b2 = (const float*)d_in[6];
    const float* W3 = (const float*)d_in[7];
    const float* b3 = (const float*)d_in[8];
    const float* W4 = (const float*)d_in[9];
    const float* b4 = (const float*)d_in[10];
    float* out = (float*)d_out;

    // created once on the first (non-capture) correctness call; host objects only
    static cudaStream_t s_side = 0;
    static cudaEvent_t  ev_fork = 0, ev_join = 0;
    if (!s_side) {
        cudaStreamCreateWithFlags(&s_side, cudaStreamNonBlocking);
        cudaEventCreateWithFlags(&ev_fork, cudaEventDisableTiming);
        cudaEventCreateWithFlags(&ev_join, cudaEventDisableTiming);
    }

    // fork: gemm runs on side stream, independent of CSR build
    cudaEventRecord(ev_fork, 0);
    cudaStreamWaitEvent(s_side, ev_fork, 0);
    k_gemm<<<6250, 256, 0, s_side>>>(x, W1);
    cudaEventRecord(ev_join, s_side);

    // main stream: CSR build
    k_init<<<NBLK, 256>>>(ei);
    k_scatter<<<NE / 1024, 256>>>(ei, ew);

    // join: agg chain needs both t0 (gemm) and csr (scatter)
    cudaStreamWaitEvent(0, ev_join, 0);

    k_agg1<<<(NN * 4 + 255) / 256, 256>>>(b1, W2);
    k_agg2<<<NN * 8 / 256, 256>>>(b2, W3);
    k_agg3<<<(NN * 4 + 255) / 256, 256>>>(b3, W4);
    k_agg4<<<NN * 8 / 256, 256>>>(b4, out);
}